// round 15
// baseline (speedup 1.0000x reference)
#include <cuda_runtime.h>
#include <cuda_fp16.h>
#include <math.h>

// ===== problem constants (DSA_5866925326622) =====
#define BB   8
#define CC   256
#define NN   4096
#define KK   1024
#define NH   8
#define HD   32
#define CH   64

// ===== persistent scratch (device globals; allocation-free) =====
__device__ float g_imp  [BB * NN];
__device__ int   g_topidx[BB * KK];
__device__ int   g_pos2k [BB * NN];
__device__ float g_xsp  [BB * KK * CC];
__device__ float g_q    [BB * KK * CC];
__device__ float g_k    [BB * KK * CC];
__device__ float g_v    [BB * KK * CC];
__device__ float g_ao   [BB * KK * CC];
__device__ float g_ps   [BB * KK * CC];
__device__ float g_enh  [BB * KK * CC];

// ===== mma / ldmatrix wrappers =====
__device__ __forceinline__ void mma_tf32(float* d,
                                         unsigned a0, unsigned a1, unsigned a2, unsigned a3,
                                         unsigned b0, unsigned b1)
{
    asm volatile(
        "mma.sync.aligned.m16n8k8.row.col.f32.tf32.tf32.f32 "
        "{%0,%1,%2,%3}, {%4,%5,%6,%7}, {%8,%9}, {%0,%1,%2,%3};\n"
        : "+f"(d[0]), "+f"(d[1]), "+f"(d[2]), "+f"(d[3])
        : "r"(a0), "r"(a1), "r"(a2), "r"(a3), "r"(b0), "r"(b1));
}

__device__ __forceinline__ void mma_bf16(float* d,
                                         unsigned a0, unsigned a1, unsigned a2, unsigned a3,
                                         unsigned b0, unsigned b1)
{
    asm volatile(
        "mma.sync.aligned.m16n8k16.row.col.f32.bf16.bf16.f32 "
        "{%0,%1,%2,%3}, {%4,%5,%6,%7}, {%8,%9}, {%0,%1,%2,%3};\n"
        : "+f"(d[0]), "+f"(d[1]), "+f"(d[2]), "+f"(d[3])
        : "r"(a0), "r"(a1), "r"(a2), "r"(a3), "r"(b0), "r"(b1));
}

__device__ __forceinline__ void mma_f16(float* d,
                                        unsigned a0, unsigned a1, unsigned a2, unsigned a3,
                                        unsigned b0, unsigned b1)
{
    asm volatile(
        "mma.sync.aligned.m16n8k16.row.col.f32.f16.f16.f32 "
        "{%0,%1,%2,%3}, {%4,%5,%6,%7}, {%8,%9}, {%0,%1,%2,%3};\n"
        : "+f"(d[0]), "+f"(d[1]), "+f"(d[2]), "+f"(d[3])
        : "r"(a0), "r"(a1), "r"(a2), "r"(a3), "r"(b0), "r"(b1));
}

// one instruction = four 8x8 b16 matrices
__device__ __forceinline__ void ldsm_x4(unsigned& r0, unsigned& r1,
                                        unsigned& r2, unsigned& r3, unsigned addr)
{
    asm volatile(
        "ldmatrix.sync.aligned.m8n8.x4.shared.b16 {%0,%1,%2,%3}, [%4];"
        : "=r"(r0), "=r"(r1), "=r"(r2), "=r"(r3) : "r"(addr));
}

__device__ __forceinline__ unsigned smem_addr(const void* p)
{
    return (unsigned)__cvta_generic_to_shared(p);
}

// exact split into two tf32-representable parts
__device__ __forceinline__ void tf32_split(float x, unsigned& hi, unsigned& lo)
{
    unsigned h = __float_as_uint(x) & 0xFFFFE000u;
    hi = h;
    lo = __float_as_uint(x - __uint_as_float(h));
}

// word.lo = first arg (even-k element), word.hi = second arg (odd-k element)
__device__ __forceinline__ unsigned pack_bf16x2(float e, float o)
{
    unsigned r;
    asm("cvt.rn.bf16x2.f32 %0, %1, %2;" : "=r"(r) : "f"(o), "f"(e));
    return r;
}

__device__ __forceinline__ unsigned pack_f16x2(float e, float o)
{
    unsigned r;
    asm("cvt.rn.f16x2.f32 %0, %1, %2;" : "=r"(r) : "f"(o), "f"(e));
    return r;
}

__device__ __forceinline__ float f16_rn_f(float x)
{
    return __half2float(__float2half_rn(x));
}

// ===== kernel 1: importance net, 3-term tf32 split (fp32-exact; feeds top-K) =====
__global__ void importance_mma_kernel(const float* __restrict__ x,
                                      const float* __restrict__ bmap,
                                      const float* __restrict__ w1,
                                      const float* __restrict__ b1,
                                      const float* __restrict__ w2,
                                      const float* __restrict__ b2,
                                      float* __restrict__ imp,
                                      float* __restrict__ imp_out)
{
    __shared__ union {
        struct { float As[32 * 132]; float Ws[64 * 36]; } t;
        float Hs[128 * 65];
    } u;
    __shared__ float b1s[64], w2s[64];

    const int tid  = threadIdx.x;   // 256
    const int lane = tid & 31;
    const int warp = tid >> 5;
    const int wm = warp >> 1, wn = warp & 1;
    const int grp = lane >> 2, tig = lane & 3;

    const int b  = blockIdx.x >> 5;
    const int p0 = (blockIdx.x & 31) * 128;

    if (tid < 64) { b1s[tid] = b1[tid]; w2s[tid] = w2[tid]; }

    float acc[2][4][4];
#pragma unroll
    for (int mt = 0; mt < 2; mt++)
#pragma unroll
        for (int nt = 0; nt < 4; nt++)
#pragma unroll
            for (int j = 0; j < 4; j++) acc[mt][nt][j] = 0.f;

    for (int c0 = 0; c0 < CC; c0 += 32) {
        __syncthreads();
#pragma unroll
        for (int i = 0; i < 4; i++) {
            int idx = tid + i * 256;
            int cl = idx >> 5, p4 = (idx & 31) * 4;
            float4 v = *(const float4*)(x + (((size_t)(b * CC + c0 + cl)) << 12) + p0 + p4);
            float* d = &u.t.As[cl * 132 + p4];
            d[0] = v.x; d[1] = v.y; d[2] = v.z; d[3] = v.w;
        }
#pragma unroll
        for (int i = 0; i < 2; i++) {
            int idx = tid + i * 256;
            int j = idx >> 3, c4 = (idx & 7) * 4;
            float4 v = *(const float4*)(w1 + j * CC + c0 + c4);
            float* d = &u.t.Ws[j * 36 + c4];
            d[0] = v.x; d[1] = v.y; d[2] = v.z; d[3] = v.w;
        }
        __syncthreads();

#pragma unroll
        for (int kc = 0; kc < 4; kc++) {
            unsigned ah[2][4], al[2][4];
#pragma unroll
            for (int mt = 0; mt < 2; mt++) {
                int row = wm * 32 + mt * 16 + grp;
                int col = kc * 8 + tig;
                tf32_split(u.t.As[col * 132 + row],           ah[mt][0], al[mt][0]);
                tf32_split(u.t.As[col * 132 + row + 8],       ah[mt][1], al[mt][1]);
                tf32_split(u.t.As[(col + 4) * 132 + row],     ah[mt][2], al[mt][2]);
                tf32_split(u.t.As[(col + 4) * 132 + row + 8], ah[mt][3], al[mt][3]);
            }
#pragma unroll
            for (int nt = 0; nt < 4; nt++) {
                int n = wn * 32 + nt * 8 + grp;
                int col = kc * 8 + tig;
                unsigned bh0, bl0, bh1, bl1;
                tf32_split(u.t.Ws[n * 36 + col],     bh0, bl0);
                tf32_split(u.t.Ws[n * 36 + col + 4], bh1, bl1);
#pragma unroll
                for (int mt = 0; mt < 2; mt++) {
                    mma_tf32(acc[mt][nt], ah[mt][0], ah[mt][1], ah[mt][2], ah[mt][3], bh0, bh1);
                    mma_tf32(acc[mt][nt], ah[mt][0], ah[mt][1], ah[mt][2], ah[mt][3], bl0, bl1);
                    mma_tf32(acc[mt][nt], al[mt][0], al[mt][1], al[mt][2], al[mt][3], bh0, bh1);
                }
            }
        }
    }
    __syncthreads();

#pragma unroll
    for (int mt = 0; mt < 2; mt++) {
#pragma unroll
        for (int nt = 0; nt < 4; nt++) {
#pragma unroll
            for (int j = 0; j < 4; j++) {
                int row = wm * 32 + mt * 16 + grp + ((j >= 2) ? 8 : 0);
                int col = wn * 32 + nt * 8 + tig * 2 + (j & 1);
                float v = acc[mt][nt][j] + b1s[col];
                u.Hs[row * 65 + col] = 0.5f * v * (1.0f + erff(v * 0.70710678118654752f));
            }
        }
    }
    __syncthreads();

    const int row = tid >> 1;
    const int jh  = (tid & 1) * 32;
    float s = 0.f;
#pragma unroll
    for (int jj = 0; jj < 32; jj++) s += u.Hs[row * 65 + jh + jj] * w2s[jh + jj];
    s += __shfl_xor_sync(0xffffffff, s, 1);
    if ((tid & 1) == 0) {
        float z  = s + b2[0];
        float sg = 1.0f / (1.0f + __expf(-z));
        float val = sg + 0.5f * bmap[(b << 12) + p0 + row];
        imp[(b << 12) + p0 + row] = val;
        if (imp_out) imp_out[(b << 12) + p0 + row] = val;
    }
}

// ===== kernel 2: exact top-K, bitonic (jax tie-break order) =====
__global__ void topk_kernel(const float* __restrict__ imp,
                            int* __restrict__ topidx,
                            int* __restrict__ pos2k)
{
    __shared__ unsigned long long keys[NN];
    __shared__ int idxs[KK];
    const int tid = threadIdx.x;  // 1024
    const int b = blockIdx.x;

    for (int i = tid; i < NN; i += 1024) {
        unsigned fb = __float_as_uint(imp[(b << 12) + i]);
        keys[i] = ((unsigned long long)fb << 32) | (unsigned)(NN - 1 - i);
        pos2k[(b << 12) + i] = -1;
    }
    __syncthreads();

    for (int k2 = 2; k2 <= NN; k2 <<= 1)
        for (int j = k2 >> 1; j > 0; j >>= 1) {
            for (int t = tid; t < NN; t += 1024) {
                int ixj = t ^ j;
                if (ixj > t) {
                    unsigned long long a = keys[t], c = keys[ixj];
                    if ((a < c) == ((t & k2) == 0)) { keys[t] = c; keys[ixj] = a; }
                }
            }
            __syncthreads();
        }

    idxs[tid] = (NN - 1) - (int)(keys[tid] & 0xFFFFFFFFull);
    __syncthreads();
    for (int k2 = 2; k2 <= KK; k2 <<= 1)
        for (int j = k2 >> 1; j > 0; j >>= 1) {
            int ixj = tid ^ j;
            if (ixj > tid) {
                int a = idxs[tid], c = idxs[ixj];
                if ((a > c) == ((tid & k2) == 0)) { idxs[tid] = c; idxs[ixj] = a; }
            }
            __syncthreads();
        }

    int p = idxs[tid];
    topidx[(b << 10) + tid] = p;
    pos2k[(b << 12) + p] = tid;
}

// ===== kernel 3: gather (smem transpose) =====
__global__ void gather_kernel(const float* __restrict__ x,
                              const int* __restrict__ topidx,
                              float* __restrict__ xsp)
{
    __shared__ float sm[32][33];
    const int k0 = blockIdx.x * 32;
    const int c0 = blockIdx.y * 32;
    const int b  = blockIdx.z;
    const int tid = threadIdx.x;
    const int l = tid & 31, g = tid >> 5;

    int p = topidx[(b << 10) + k0 + l];
#pragma unroll
    for (int r = 0; r < 4; r++) {
        int cl = g + r * 8;
        sm[cl][l] = x[(((size_t)(b * CC + c0 + cl)) << 12) + p];
    }
    __syncthreads();
#pragma unroll
    for (int r = 0; r < 4; r++) {
        int kl = g + r * 8;
        xsp[(((size_t)((b << 10) + k0 + kl)) << 8) + c0 + l] = sm[l][kl];
    }
}

// ===== kernel 4: fp16 2-term GEMM, m16n8k16, double-buffered, ldmatrix fragments =====
__global__ void __launch_bounds__(256, 3)
gemm_f16_kernel(const float* __restrict__ A,
                const float* __restrict__ W0, const float* __restrict__ B0, float* __restrict__ C0,
                const float* __restrict__ W1, const float* __restrict__ B1, float* __restrict__ C1,
                const float* __restrict__ W2, const float* __restrict__ B2, float* __restrict__ C2,
                int M, int Nn, int Kd)
{
    const float* W    = W0;
    const float* bias = B0;
    float*       Cout = C0;
    if (blockIdx.z == 1)      { W = W1; bias = B1; Cout = C1; }
    else if (blockIdx.z == 2) { W = W2; bias = B2; Cout = C2; }

    __shared__ __align__(16) unsigned Ahp[2][128 * 20];
    __shared__ __align__(16) unsigned Whp[2][64 * 20];
    __shared__ __align__(16) unsigned Wlp[2][64 * 20];

    const int tid  = threadIdx.x;
    const int lane = tid & 31;
    const int warp = tid >> 5;
    const int wm = warp >> 1, wn = warp & 1;
    const int grp = lane >> 2, tig = lane & 3;
    const int rl   = lane & 7;      // row-in-matrix for ldmatrix
    const int half = lane >> 3;     // matrix id 0..3

    const int bm = blockIdx.y * 128;
    const int bn = blockIdx.x * 64;

    float acc[2][4][4];
#pragma unroll
    for (int mt = 0; mt < 2; mt++)
#pragma unroll
        for (int nt = 0; nt < 4; nt++)
#pragma unroll
            for (int j = 0; j < 4; j++) acc[mt][nt][j] = 0.f;

    int buf = 0;
    for (int c0 = 0; c0 < Kd; c0 += 32, buf ^= 1) {
#pragma unroll
        for (int i = 0; i < 4; i++) {
            int idx = tid + i * 256;
            int r = idx >> 3, c4 = (idx & 7) * 4;
            float4 v = *(const float4*)(A + (size_t)(bm + r) * Kd + c0 + c4);
            unsigned* d = &Ahp[buf][r * 20 + (c4 >> 1)];
            d[0] = pack_f16x2(v.x, v.y);
            d[1] = pack_f16x2(v.z, v.w);
        }
#pragma unroll
        for (int i = 0; i < 2; i++) {
            int idx = tid + i * 256;
            int r = idx >> 3, c4 = (idx & 7) * 4;
            float4 v = *(const float4*)(W + (size_t)(bn + r) * Kd + c0 + c4);
            float h0 = f16_rn_f(v.x), h1 = f16_rn_f(v.y);
            float h2 = f16_rn_f(v.z), h3 = f16_rn_f(v.w);
            unsigned* dh = &Whp[buf][r * 20 + (c4 >> 1)];
            unsigned* dl = &Wlp[buf][r * 20 + (c4 >> 1)];
            dh[0] = pack_f16x2(h0, h1);
            dh[1] = pack_f16x2(h2, h3);
            dl[0] = pack_f16x2(v.x - h0, v.y - h1);
            dl[1] = pack_f16x2(v.z - h2, v.w - h3);
        }
        __syncthreads();

        unsigned abase  = smem_addr(&Ahp[buf][0]);
        unsigned whbase = smem_addr(&Whp[buf][0]);
        unsigned wlbase = smem_addr(&Wlp[buf][0]);

#pragma unroll
        for (int kc = 0; kc < 2; kc++) {
            // A fragments: one ldmatrix.x4 per mt
            unsigned af[2][4];
#pragma unroll
            for (int mt = 0; mt < 2; mt++) {
                int row = wm * 32 + mt * 16 + (half & 1) * 8 + rl;
                ldsm_x4(af[mt][0], af[mt][1], af[mt][2], af[mt][3],
                        abase + row * 80 + kc * 32 + (half >> 1) * 16);
            }
            // W fragments: one ldmatrix.x4 covers two adjacent nt blocks
#pragma unroll
            for (int ntp = 0; ntp < 2; ntp++) {
                int row = wn * 32 + ntp * 16 + (half >> 1) * 8 + rl;
                unsigned rowoff = row * 80 + kc * 32 + (half & 1) * 16;
                unsigned wh0, wh1, wh2, wh3, wl0, wl1, wl2, wl3;
                ldsm_x4(wh0, wh1, wh2, wh3, whbase + rowoff);
                ldsm_x4(wl0, wl1, wl2, wl3, wlbase + rowoff);
#pragma unroll
                for (int mt = 0; mt < 2; mt++) {
                    mma_f16(acc[mt][2 * ntp],     af[mt][0], af[mt][1], af[mt][2], af[mt][3], wh0, wh1);
                    mma_f16(acc[mt][2 * ntp],     af[mt][0], af[mt][1], af[mt][2], af[mt][3], wl0, wl1);
                    mma_f16(acc[mt][2 * ntp + 1], af[mt][0], af[mt][1], af[mt][2], af[mt][3], wh2, wh3);
                    mma_f16(acc[mt][2 * ntp + 1], af[mt][0], af[mt][1], af[mt][2], af[mt][3], wl2, wl3);
                }
            }
        }
    }

#pragma unroll
    for (int mt = 0; mt < 2; mt++) {
#pragma unroll
        for (int nt = 0; nt < 4; nt++) {
            int row = bm + wm * 32 + mt * 16 + grp;
            int col = bn + wn * 32 + nt * 8 + tig * 2;
            float2 bv = *(const float2*)(bias + col);
            float2 o0 = { acc[mt][nt][0] + bv.x, acc[mt][nt][1] + bv.y };
            float2 o1 = { acc[mt][nt][2] + bv.x, acc[mt][nt][3] + bv.y };
            *(float2*)(Cout + (size_t)row * Nn + col)       = o0;
            *(float2*)(Cout + (size_t)(row + 8) * Nn + col) = o1;
        }
    }
}

// ===== kernel 5: flash attention (bf16 MMA, double-buffered, ldmatrix K/P) =====
__global__ void __launch_bounds__(128, 5)
attn_bf16_kernel(const float* __restrict__ Q,
                 const float* __restrict__ Kb,
                 const float* __restrict__ Vb,
                 float* __restrict__ O)
{
    __shared__ __align__(16) unsigned Kbf[2][64 * 20];
    __shared__ __align__(16) unsigned Vp [2][32 * 40];
    __shared__ __align__(16) unsigned Pp [64 * 36];   // P; also Q staging (stride 20)

    const int tid  = threadIdx.x;   // 128
    const int lane = tid & 31;
    const int warp = tid >> 5;
    const int grp = lane >> 2, tig = lane & 3;
    const int rl   = lane & 7;
    const int half = lane >> 3;
    const int wr = warp * 16;

    const int m0 = blockIdx.x * 64;
    const int hh = blockIdx.y;
    const int b  = blockIdx.z;
    const size_t base = (size_t)b * KK * CC + hh * HD;
    const float scale = 0.17677669529663687f;

#pragma unroll
    for (int i = 0; i < 4; i++) {
        int idx = tid + i * 128;
        int r = idx >> 3, c4 = (idx & 7) * 4;
        float4 v = *(const float4*)(Q + base + (size_t)(m0 + r) * CC + c4);
        unsigned* d = &Pp[r * 20 + (c4 >> 1)];
        d[0] = pack_bf16x2(v.x * scale, v.y * scale);
        d[1] = pack_bf16x2(v.z * scale, v.w * scale);
    }
    __syncthreads();

    unsigned qf[2][4];
#pragma unroll
    for (int kc = 0; kc < 2; kc++) {
        int cp = kc * 8 + tig;
        qf[kc][0] = Pp[(wr + grp) * 20 + cp];
        qf[kc][1] = Pp[(wr + grp + 8) * 20 + cp];
        qf[kc][2] = Pp[(wr + grp) * 20 + cp + 4];
        qf[kc][3] = Pp[(wr + grp + 8) * 20 + cp + 4];
    }
    __syncthreads();

    float mr0 = -INFINITY, mr1 = -INFINITY, l0 = 0.f, l1 = 0.f;
    float oacc[4][4];
#pragma unroll
    for (int dt = 0; dt < 4; dt++)
#pragma unroll
        for (int j = 0; j < 4; j++) oacc[dt][j] = 0.f;

    float4 rk[4], rv0[2], rv1[2];
#pragma unroll
    for (int i = 0; i < 4; i++) {
        int idx = tid + i * 128;
        int r = idx >> 3, c4 = (idx & 7) * 4;
        rk[i] = *(const float4*)(Kb + base + (size_t)r * CC + c4);
    }
#pragma unroll
    for (int i = 0; i < 2; i++) {
        int idx = tid + i * 128;
        int j = idx >> 3, c4 = (idx & 7) * 4;
        rv0[i] = *(const float4*)(Vb + base + (size_t)(2 * j)     * CC + c4);
        rv1[i] = *(const float4*)(Vb + base + (size_t)(2 * j + 1) * CC + c4);
    }

    const unsigned pbase = smem_addr(&Pp[0]);

    int buf = 0;
    for (int n0 = 0; n0 < KK; n0 += 64, buf ^= 1) {
#pragma unroll
        for (int i = 0; i < 4; i++) {
            int idx = tid + i * 128;
            int r = idx >> 3, c4 = (idx & 7) * 4;
            unsigned* d = &Kbf[buf][r * 20 + (c4 >> 1)];
            d[0] = pack_bf16x2(rk[i].x, rk[i].y);
            d[1] = pack_bf16x2(rk[i].z, rk[i].w);
        }
#pragma unroll
        for (int i = 0; i < 2; i++) {
            int idx = tid + i * 128;
            int j = idx >> 3, c4 = (idx & 7) * 4;
            unsigned* d = &Vp[buf][j * 40 + c4];
            d[0] = pack_bf16x2(rv0[i].x, rv1[i].x);
            d[1] = pack_bf16x2(rv0[i].y, rv1[i].y);
            d[2] = pack_bf16x2(rv0[i].z, rv1[i].z);
            d[3] = pack_bf16x2(rv0[i].w, rv1[i].w);
        }
        __syncthreads();

        if (n0 + 64 < KK) {
#pragma unroll
            for (int i = 0; i < 4; i++) {
                int idx = tid + i * 128;
                int r = idx >> 3, c4 = (idx & 7) * 4;
                rk[i] = *(const float4*)(Kb + base + (size_t)(n0 + 64 + r) * CC + c4);
            }
#pragma unroll
            for (int i = 0; i < 2; i++) {
                int idx = tid + i * 128;
                int j = idx >> 3, c4 = (idx & 7) * 4;
                rv0[i] = *(const float4*)(Vb + base + (size_t)(n0 + 64 + 2 * j)     * CC + c4);
                rv1[i] = *(const float4*)(Vb + base + (size_t)(n0 + 64 + 2 * j + 1) * CC + c4);
            }
        }

        const unsigned kbase = smem_addr(&Kbf[buf][0]);
        const unsigned vbase_ok = 0;  (void)vbase_ok;

        // S = Q K^T : ldmatrix.x4 per (kc, nt-pair)
        float s[8][4];
#pragma unroll
        for (int nt = 0; nt < 8; nt++) {
            s[nt][0] = s[nt][1] = s[nt][2] = s[nt][3] = 0.f;
        }
#pragma unroll
        for (int kc = 0; kc < 2; kc++) {
#pragma unroll
            for (int ntp = 0; ntp < 4; ntp++) {
                int row = ntp * 16 + (half >> 1) * 8 + rl;
                unsigned kb0, kb1, kb2, kb3;
                ldsm_x4(kb0, kb1, kb2, kb3,
                        kbase + row * 80 + kc * 32 + (half & 1) * 16);
                mma_bf16(s[2 * ntp],     qf[kc][0], qf[kc][1], qf[kc][2], qf[kc][3], kb0, kb1);
                mma_bf16(s[2 * ntp + 1], qf[kc][0], qf[kc][1], qf[kc][2], qf[kc][3], kb2, kb3);
            }
        }

        float tm0 = -INFINITY, tm1 = -INFINITY;
#pragma unroll
        for (int nt = 0; nt < 8; nt++) {
            tm0 = fmaxf(tm0, fmaxf(s[nt][0], s[nt][1]));
            tm1 = fmaxf(tm1, fmaxf(s[nt][2], s[nt][3]));
        }
        tm0 = fmaxf(tm0, __shfl_xor_sync(0xffffffff, tm0, 1));
        tm0 = fmaxf(tm0, __shfl_xor_sync(0xffffffff, tm0, 2));
        tm1 = fmaxf(tm1, __shfl_xor_sync(0xffffffff, tm1, 1));
        tm1 = fmaxf(tm1, __shfl_xor_sync(0xffffffff, tm1, 2));

        float mn0 = fmaxf(mr0, tm0), mn1 = fmaxf(mr1, tm1);
        float corr0 = __expf(mr0 - mn0), corr1 = __expf(mr1 - mn1);
        float ps0 = 0.f, ps1 = 0.f;
#pragma unroll
        for (int nt = 0; nt < 8; nt++) {
            float p0 = __expf(s[nt][0] - mn0);
            float p1 = __expf(s[nt][1] - mn0);
            float p2 = __expf(s[nt][2] - mn1);
            float p3 = __expf(s[nt][3] - mn1);
            ps0 += p0 + p1; ps1 += p2 + p3;
            int cp = nt * 4 + tig;
            Pp[(wr + grp) * 36 + cp]     = pack_bf16x2(p0, p1);
            Pp[(wr + grp + 8) * 36 + cp] = pack_bf16x2(p2, p3);
        }
        ps0 += __shfl_xor_sync(0xffffffff, ps0, 1);
        ps0 += __shfl_xor_sync(0xffffffff, ps0, 2);
        ps1 += __shfl_xor_sync(0xffffffff, ps1, 1);
        ps1 += __shfl_xor_sync(0xffffffff, ps1, 2);
        l0 = l0 * corr0 + ps0;
        l1 = l1 * corr1 + ps1;
#pragma unroll
        for (int dt = 0; dt < 4; dt++) {
            oacc[dt][0] *= corr0; oacc[dt][1] *= corr0;
            oacc[dt][2] *= corr1; oacc[dt][3] *= corr1;
        }
        mr0 = mn0; mr1 = mn1;
        __syncwarp();

        // O += P V  (P via ldmatrix.x4; V scalar — packing axis is transposed)
#pragma unroll
        for (int kc = 0; kc < 4; kc++) {
            int prow = wr + (half & 1) * 8 + rl;
            unsigned a0, a1, a2, a3;
            ldsm_x4(a0, a1, a2, a3,
                    pbase + prow * 144 + kc * 32 + (half >> 1) * 16);
#pragma unroll
            for (int dt = 0; dt < 4; dt++) {
                unsigned vb0 = Vp[buf][(kc * 8 + tig) * 40 + dt * 8 + grp];
                unsigned vb1 = Vp[buf][(kc * 8 + tig + 4) * 40 + dt * 8 + grp];
                mma_bf16(oacc[dt], a0, a1, a2, a3, vb0, vb1);
            }
        }
        __syncwarp();
    }

    const float inv0 = 1.0f / l0, inv1 = 1.0f / l1;
    const int row = m0 + wr + grp;
#pragma unroll
    for (int dt = 0; dt < 4; dt++) {
        int col = dt * 8 + tig * 2;
        float2 o0 = { oacc[dt][0] * inv0, oacc[dt][1] * inv0 };
        float2 o1 = { oacc[dt][2] * inv1, oacc[dt][3] * inv1 };
        *(float2*)(O + base + (size_t)row * CC + col)       = o0;
        *(float2*)(O + base + (size_t)(row + 8) * CC + col) = o1;
    }
}

// ===== kernel 6: residual + LayerNorm =====
__global__ void ln_kernel(const float* __restrict__ P,
                          const float* __restrict__ X,
                          const float* __restrict__ g,
                          const float* __restrict__ beta,
                          float* __restrict__ E)
{
    const int row = blockIdx.x;
    const int c = threadIdx.x;
    const size_t off = (size_t)row * CC + c;
    float y = P[off] + X[off];
    float v1 = y, v2 = y * y;
#pragma unroll
    for (int o = 16; o > 0; o >>= 1) {
        v1 += __shfl_xor_sync(0xffffffff, v1, o);
        v2 += __shfl_xor_sync(0xffffffff, v2, o);
    }
    __shared__ float s1[8], s2[8];
    int w = c >> 5, ln = c & 31;
    if (ln == 0) { s1[w] = v1; s2[w] = v2; }
    __syncthreads();
    float sum = 0.f, sq = 0.f;
#pragma unroll
    for (int i = 0; i < 8; i++) { sum += s1[i]; sq += s2[i]; }
    float mu  = sum * (1.0f / CC);
    float var = sq * (1.0f / CC) - mu * mu;
    float rs  = rsqrtf(var + 1e-5f);
    E[off] = (y - mu) * rs * g[c] + beta[c];
}

// ===== kernel 7: output assembly =====
__global__ void scatter_kernel(const float* __restrict__ X,
                               const int* __restrict__ pos2k,
                               const float* __restrict__ E,
                               float* __restrict__ out)
{
    const int gid = blockIdx.x * 256 + threadIdx.x;
    const int b = gid >> 20;
    const int c = (gid >> 12) & (CC - 1);
    const int p = gid & (NN - 1);
    int k = pos2k[(b << 12) + p];
    out[gid] = (k >= 0) ? E[(size_t)(((b << 10) + k) << 8) + c] : X[gid];
}

// ===== host launch =====
extern "C" void kernel_launch(void* const* d_in, const int* in_sizes, int n_in,
                              void* d_out, int out_size)
{
    const float* x    = (const float*)d_in[0];
    const float* bmap = (const float*)d_in[1];
    const float* iw1  = (const float*)d_in[2];
    const float* ib1  = (const float*)d_in[3];
    const float* iw2  = (const float*)d_in[4];
    const float* ib2  = (const float*)d_in[5];
    const float* wq   = (const float*)d_in[6];
    const float* bq   = (const float*)d_in[7];
    const float* wk   = (const float*)d_in[8];
    const float* bk   = (const float*)d_in[9];
    const float* wv   = (const float*)d_in[10];
    const float* bv   = (const float*)d_in[11];
    const float* wo   = (const float*)d_in[12];
    const float* bo   = (const float*)d_in[13];
    const float* lng  = (const float*)d_in[14];
    const float* lnb  = (const float*)d_in[15];

    static float *P_imp = nullptr, *P_xsp, *P_q, *P_k, *P_v, *P_ao, *P_ps, *P_enh;
    static int *P_topidx, *P_pos2k;
    if (!P_imp) {
        cudaGetSymbolAddress((void**)&P_imp,    g_imp);
        cudaGetSymbolAddress((void**)&P_topidx, g_topidx);
        cudaGetSymbolAddress((void**)&P_pos2k,  g_pos2k);
        cudaGetSymbolAddress((void**)&P_xsp,    g_xsp);
        cudaGetSymbolAddress((void**)&P_q,      g_q);
        cudaGetSymbolAddress((void**)&P_k,      g_k);
        cudaGetSymbolAddress((void**)&P_v,      g_v);
        cudaGetSymbolAddress((void**)&P_ao,     g_ao);
        cudaGetSymbolAddress((void**)&P_ps,     g_ps);
        cudaGetSymbolAddress((void**)&P_enh,    g_enh);
    }

    float* out = (float*)d_out;
    float* imp_out = (out_size >= BB * CC * NN + BB * NN) ? out + (size_t)BB * CC * NN
                                                          : nullptr;

    importance_mma_kernel<<<BB * 32, 256>>>(x, bmap, iw1, ib1, iw2, ib2,
                                            P_imp, imp_out);
    topk_kernel<<<BB, 1024>>>(P_imp, P_topidx, P_pos2k);

    dim3 grid_gather(KK / 32, CC / 32, BB);
    gather_kernel<<<grid_gather, 256>>>(x, P_topidx, P_xsp);

    dim3 grid_qkv(CC / 64, (BB * KK) / 128, 3);
    gemm_f16_kernel<<<grid_qkv, 256>>>(P_xsp,
                                       wq, bq, P_q,
                                       wk, bk, P_k,
                                       wv, bv, P_v,
                                       BB * KK, CC, CC);

    dim3 grid_attn(KK / 64, NH, BB);
    attn_bf16_kernel<<<grid_attn, 128>>>(P_q, P_k, P_v, P_ao);

    dim3 grid_o(CC / 64, (BB * KK) / 128, 1);
    gemm_f16_kernel<<<grid_o, 256>>>(P_ao,
                                     wo, bo, P_ps,
                                     wo, bo, P_ps,
                                     wo, bo, P_ps,
                                     BB * KK, CC, CC);

    ln_kernel<<<BB * KK, 256>>>(P_ps, P_xsp, lng, lnb, P_enh);
    scatter_kernel<<<(BB * CC * NN) / 256, 256>>>(x, P_pos2k, P_enh, out);
}